// round 1
// baseline (speedup 1.0000x reference)
#include <cuda_runtime.h>

// Problem constants
#define HH 2048
#define WW 2048
#define NPIX (HH * WW)          // 4,194,304 pixels
#define NCH 8

constexpr int S0 = 1024, S1 = 512, S2 = 256, S3 = 128;
constexpr int OFF0 = 0;
constexpr int OFF1 = OFF0 + S0 * S0 * NCH;
constexpr int OFF2 = OFF1 + S1 * S1 * NCH;
constexpr int OFF3 = OFF2 + S2 * S2 * NCH;
constexpr int SCRATCH_ELEMS = OFF3 + S3 * S3 * NCH;   // 11,141,120 floats = 44.56 MB

// Static device scratch: transposed (channels-last) texture pyramid.
// [S,S,C] layout => one texel = 32 contiguous bytes = exactly one 32B L2 sector.
__device__ float g_tex_t[SCRATCH_ELEMS];

// ---------------------------------------------------------------------------
// Transpose [C,S,S] -> [S,S,C].  Reads coalesced per-channel, writes 2x st.128.
// ---------------------------------------------------------------------------
__global__ void transpose_tex_kernel(const float* __restrict__ src,
                                     float* __restrict__ dst, int n /* = S*S */) {
    int idx = blockIdx.x * blockDim.x + threadIdx.x;
    if (idx >= n) return;
    float v[NCH];
#pragma unroll
    for (int c = 0; c < NCH; c++) v[c] = src[c * n + idx];
    float4* d = reinterpret_cast<float4*>(dst + (size_t)idx * NCH);
    d[0] = make_float4(v[0], v[1], v[2], v[3]);
    d[1] = make_float4(v[4], v[5], v[6], v[7]);
}

// ---------------------------------------------------------------------------
// One bilinear tap from a channels-last texture of size S x S.
// align_corners=False with grid = uv*2-1 collapses to: g = uv*S - 0.5
// padding_mode='zeros': out-of-range corners contribute 0.
// ---------------------------------------------------------------------------
template <int S>
__device__ __forceinline__ void sample_one(const float* __restrict__ base,
                                           float u, float v, float acc[NCH]) {
    float gx = u * (float)S - 0.5f;
    float gy = v * (float)S - 0.5f;
    float xf = floorf(gx);
    float yf = floorf(gy);
    int x0 = (int)xf, y0 = (int)yf;
    int x1 = x0 + 1,  y1 = y0 + 1;
    float fx = gx - xf;
    float fy = gy - yf;

    bool vx0 = (x0 >= 0) & (x0 < S);
    bool vx1 = (x1 >= 0) & (x1 < S);
    bool vy0 = (y0 >= 0) & (y0 < S);
    bool vy1 = (y1 >= 0) & (y1 < S);

    const float4 z4 = make_float4(0.f, 0.f, 0.f, 0.f);
    float4 a00 = z4, b00 = z4, a10 = z4, b10 = z4;
    float4 a01 = z4, b01 = z4, a11 = z4, b11 = z4;

    // Issue all 4 corner loads (2x float4 each) up front for MLP.
    if (vy0 & vx0) {
        const float4* p = reinterpret_cast<const float4*>(base + ((size_t)y0 * S + x0) * NCH);
        a00 = p[0]; b00 = p[1];
    }
    if (vy0 & vx1) {
        const float4* p = reinterpret_cast<const float4*>(base + ((size_t)y0 * S + x1) * NCH);
        a10 = p[0]; b10 = p[1];
    }
    if (vy1 & vx0) {
        const float4* p = reinterpret_cast<const float4*>(base + ((size_t)y1 * S + x0) * NCH);
        a01 = p[0]; b01 = p[1];
    }
    if (vy1 & vx1) {
        const float4* p = reinterpret_cast<const float4*>(base + ((size_t)y1 * S + x1) * NCH);
        a11 = p[0]; b11 = p[1];
    }

    float w00 = (1.0f - fx) * (1.0f - fy);
    float w10 = fx * (1.0f - fy);
    float w01 = (1.0f - fx) * fy;
    float w11 = fx * fy;

    acc[0] += w00 * a00.x + w10 * a10.x + w01 * a01.x + w11 * a11.x;
    acc[1] += w00 * a00.y + w10 * a10.y + w01 * a01.y + w11 * a11.y;
    acc[2] += w00 * a00.z + w10 * a10.z + w01 * a01.z + w11 * a11.z;
    acc[3] += w00 * a00.w + w10 * a10.w + w01 * a01.w + w11 * a11.w;
    acc[4] += w00 * b00.x + w10 * b10.x + w01 * b01.x + w11 * b11.x;
    acc[5] += w00 * b00.y + w10 * b10.y + w01 * b01.y + w11 * b11.y;
    acc[6] += w00 * b00.z + w10 * b10.z + w01 * b01.z + w11 * b11.z;
    acc[7] += w00 * b00.w + w10 * b10.w + w01 * b01.w + w11 * b11.w;
}

// ---------------------------------------------------------------------------
// Main kernel: 1 thread per pixel, sums 4 mip levels over all 8 channels.
// ---------------------------------------------------------------------------
__global__ void __launch_bounds__(256)
deferred_render_kernel(const float* __restrict__ uv, float* __restrict__ out) {
    int idx = blockIdx.x * blockDim.x + threadIdx.x;
    if (idx >= NPIX) return;

    float u = uv[idx];           // uv_tensor[0,0,:,:]
    float v = uv[NPIX + idx];    // uv_tensor[0,1,:,:]

    float acc[NCH];
#pragma unroll
    for (int c = 0; c < NCH; c++) acc[c] = 0.0f;

    sample_one<S0>(g_tex_t + OFF0, u, v, acc);
    sample_one<S1>(g_tex_t + OFF1, u, v, acc);
    sample_one<S2>(g_tex_t + OFF2, u, v, acc);
    sample_one<S3>(g_tex_t + OFF3, u, v, acc);

#pragma unroll
    for (int c = 0; c < NCH; c++)
        out[(size_t)c * NPIX + idx] = acc[c];
}

// ---------------------------------------------------------------------------
// Launch. Inputs per metadata order: uv_tensor, iter_nr, tex0..tex3.
// ---------------------------------------------------------------------------
extern "C" void kernel_launch(void* const* d_in, const int* in_sizes, int n_in,
                              void* d_out, int out_size) {
    const float* uv   = (const float*)d_in[0];
    // d_in[1] = iter_nr (unused)
    const float* tex0 = (const float*)d_in[2];
    const float* tex1 = (const float*)d_in[3];
    const float* tex2 = (const float*)d_in[4];
    const float* tex3 = (const float*)d_in[5];

    float* scratch;
    cudaGetSymbolAddress((void**)&scratch, g_tex_t);

    const int TB = 256;
    transpose_tex_kernel<<<(S0 * S0 + TB - 1) / TB, TB>>>(tex0, scratch + OFF0, S0 * S0);
    transpose_tex_kernel<<<(S1 * S1 + TB - 1) / TB, TB>>>(tex1, scratch + OFF1, S1 * S1);
    transpose_tex_kernel<<<(S2 * S2 + TB - 1) / TB, TB>>>(tex2, scratch + OFF2, S2 * S2);
    transpose_tex_kernel<<<(S3 * S3 + TB - 1) / TB, TB>>>(tex3, scratch + OFF3, S3 * S3);

    deferred_render_kernel<<<NPIX / TB, TB>>>(uv, (float*)d_out);
}

// round 2
// speedup vs baseline: 1.4388x; 1.4388x over previous
#include <cuda_runtime.h>

// Problem constants
#define HH 2048
#define WW 2048
#define NPIX (HH * WW)          // 4,194,304 pixels
#define NCH 8

constexpr int S0 = 1024, S1 = 512, S2 = 256, S3 = 128;
constexpr int OFF0 = 0;
constexpr int OFF1 = OFF0 + S0 * S0 * NCH;
constexpr int OFF2 = OFF1 + S1 * S1 * NCH;
constexpr int OFF3 = OFF2 + S2 * S2 * NCH;
constexpr int SCRATCH_ELEMS = OFF3 + S3 * S3 * NCH;   // 11,141,120 floats = 44.56 MB

// Static device scratch: transposed (channels-last) texture pyramid.
// [S,S,C] layout => one texel = 32 contiguous bytes = one 32B sector,
// 32B-aligned => a single LDG.E.256 per corner, one 128B line touched.
__device__ float g_tex_t[SCRATCH_ELEMS];

// ---------------------------------------------------------------------------
// 256-bit load (sm_100+): fetch a whole 32B texel in ONE instruction.
// Halves L1tex wavefront count vs 2x LDG.128.
// ---------------------------------------------------------------------------
__device__ __forceinline__ void ldg256(const float* __restrict__ p,
                                       float4& a, float4& b) {
    asm volatile("ld.global.nc.v8.f32 {%0,%1,%2,%3,%4,%5,%6,%7}, [%8];"
                 : "=f"(a.x), "=f"(a.y), "=f"(a.z), "=f"(a.w),
                   "=f"(b.x), "=f"(b.y), "=f"(b.z), "=f"(b.w)
                 : "l"(p));
}

// ---------------------------------------------------------------------------
// Transpose [C,S,S] -> [S,S,C].  Reads coalesced per-channel, writes 2x st.128.
// ---------------------------------------------------------------------------
__global__ void transpose_tex_kernel(const float* __restrict__ src,
                                     float* __restrict__ dst, int n /* = S*S */) {
    int idx = blockIdx.x * blockDim.x + threadIdx.x;
    if (idx >= n) return;
    float v[NCH];
#pragma unroll
    for (int c = 0; c < NCH; c++) v[c] = src[c * n + idx];
    float4* d = reinterpret_cast<float4*>(dst + (size_t)idx * NCH);
    d[0] = make_float4(v[0], v[1], v[2], v[3]);
    d[1] = make_float4(v[4], v[5], v[6], v[7]);
}

// ---------------------------------------------------------------------------
// One bilinear tap from a channels-last texture of size S x S.
// align_corners=False with grid = uv*2-1 collapses to: g = uv*S - 0.5
// padding_mode='zeros': out-of-range corners contribute 0.
// ---------------------------------------------------------------------------
template <int S>
__device__ __forceinline__ void sample_one(const float* __restrict__ base,
                                           float u, float v, float acc[NCH]) {
    float gx = u * (float)S - 0.5f;
    float gy = v * (float)S - 0.5f;
    float xf = floorf(gx);
    float yf = floorf(gy);
    int x0 = (int)xf, y0 = (int)yf;
    int x1 = x0 + 1,  y1 = y0 + 1;
    float fx = gx - xf;
    float fy = gy - yf;

    bool vx0 = (x0 >= 0) & (x0 < S);
    bool vx1 = (x1 >= 0) & (x1 < S);
    bool vy0 = (y0 >= 0) & (y0 < S);
    bool vy1 = (y1 >= 0) & (y1 < S);

    const float4 z4 = make_float4(0.f, 0.f, 0.f, 0.f);
    float4 a00 = z4, b00 = z4, a10 = z4, b10 = z4;
    float4 a01 = z4, b01 = z4, a11 = z4, b11 = z4;

    // Issue all 4 corner loads (1x LDG.256 each) up front for MLP.
    if (vy0 & vx0) ldg256(base + ((size_t)y0 * S + x0) * NCH, a00, b00);
    if (vy0 & vx1) ldg256(base + ((size_t)y0 * S + x1) * NCH, a10, b10);
    if (vy1 & vx0) ldg256(base + ((size_t)y1 * S + x0) * NCH, a01, b01);
    if (vy1 & vx1) ldg256(base + ((size_t)y1 * S + x1) * NCH, a11, b11);

    float w00 = (1.0f - fx) * (1.0f - fy);
    float w10 = fx * (1.0f - fy);
    float w01 = (1.0f - fx) * fy;
    float w11 = fx * fy;

    acc[0] += w00 * a00.x + w10 * a10.x + w01 * a01.x + w11 * a11.x;
    acc[1] += w00 * a00.y + w10 * a10.y + w01 * a01.y + w11 * a11.y;
    acc[2] += w00 * a00.z + w10 * a10.z + w01 * a01.z + w11 * a11.z;
    acc[3] += w00 * a00.w + w10 * a10.w + w01 * a01.w + w11 * a11.w;
    acc[4] += w00 * b00.x + w10 * b10.x + w01 * b01.x + w11 * b11.x;
    acc[5] += w00 * b00.y + w10 * b10.y + w01 * b01.y + w11 * b11.y;
    acc[6] += w00 * b00.z + w10 * b10.z + w01 * b01.z + w11 * b11.z;
    acc[7] += w00 * b00.w + w10 * b10.w + w01 * b01.w + w11 * b11.w;
}

// ---------------------------------------------------------------------------
// Main kernel: 1 thread per pixel, sums 4 mip levels over all 8 channels.
// ---------------------------------------------------------------------------
__global__ void __launch_bounds__(256)
deferred_render_kernel(const float* __restrict__ uv, float* __restrict__ out) {
    int idx = blockIdx.x * blockDim.x + threadIdx.x;
    if (idx >= NPIX) return;

    float u = uv[idx];           // uv_tensor[0,0,:,:]
    float v = uv[NPIX + idx];    // uv_tensor[0,1,:,:]

    float acc[NCH];
#pragma unroll
    for (int c = 0; c < NCH; c++) acc[c] = 0.0f;

    sample_one<S0>(g_tex_t + OFF0, u, v, acc);
    sample_one<S1>(g_tex_t + OFF1, u, v, acc);
    sample_one<S2>(g_tex_t + OFF2, u, v, acc);
    sample_one<S3>(g_tex_t + OFF3, u, v, acc);

#pragma unroll
    for (int c = 0; c < NCH; c++)
        out[(size_t)c * NPIX + idx] = acc[c];
}

// ---------------------------------------------------------------------------
// Launch. Inputs per metadata order: uv_tensor, iter_nr, tex0..tex3.
// ---------------------------------------------------------------------------
extern "C" void kernel_launch(void* const* d_in, const int* in_sizes, int n_in,
                              void* d_out, int out_size) {
    const float* uv   = (const float*)d_in[0];
    // d_in[1] = iter_nr (unused)
    const float* tex0 = (const float*)d_in[2];
    const float* tex1 = (const float*)d_in[3];
    const float* tex2 = (const float*)d_in[4];
    const float* tex3 = (const float*)d_in[5];

    float* scratch;
    cudaGetSymbolAddress((void**)&scratch, g_tex_t);

    const int TB = 256;
    transpose_tex_kernel<<<(S0 * S0 + TB - 1) / TB, TB>>>(tex0, scratch + OFF0, S0 * S0);
    transpose_tex_kernel<<<(S1 * S1 + TB - 1) / TB, TB>>>(tex1, scratch + OFF1, S1 * S1);
    transpose_tex_kernel<<<(S2 * S2 + TB - 1) / TB, TB>>>(tex2, scratch + OFF2, S2 * S2);
    transpose_tex_kernel<<<(S3 * S3 + TB - 1) / TB, TB>>>(tex3, scratch + OFF3, S3 * S3);

    deferred_render_kernel<<<NPIX / TB, TB>>>(uv, (float*)d_out);
}

// round 3
// speedup vs baseline: 2.2117x; 1.5372x over previous
#include <cuda_runtime.h>
#include <cuda_fp16.h>

// Problem constants
#define HH 2048
#define WW 2048
#define NPIX (HH * WW)          // 4,194,304 pixels
#define NCH 8

constexpr int S0 = 1024, S1 = 512, S2 = 256, S3 = 128;
// Pair-slot layout: one 32B slot per (y,x) holding fp16 texels (x) and (x+1).
// Slot stride = 8 uints (32B). Offsets in uints:
constexpr size_t POFF0 = 0;
constexpr size_t POFF1 = POFF0 + (size_t)S0 * S0 * 8;
constexpr size_t POFF2 = POFF1 + (size_t)S1 * S1 * 8;
constexpr size_t POFF3 = POFF2 + (size_t)S2 * S2 * 8;
constexpr size_t PAIR_ELEMS = POFF3 + (size_t)S3 * S3 * 8;   // 11,141,120 uints = 44.56 MB

__device__ __align__(128) unsigned int g_pairs[PAIR_ELEMS];

// ---------------------------------------------------------------------------
// 256-bit load (sm_100+), 32B-aligned: one instruction, one 32B sector.
// ---------------------------------------------------------------------------
__device__ __forceinline__ void ldg256u(const unsigned int* __restrict__ p,
                                        unsigned int r[8]) {
    asm volatile("ld.global.nc.v8.b32 {%0,%1,%2,%3,%4,%5,%6,%7}, [%8];"
                 : "=r"(r[0]), "=r"(r[1]), "=r"(r[2]), "=r"(r[3]),
                   "=r"(r[4]), "=r"(r[5]), "=r"(r[6]), "=r"(r[7])
                 : "l"(p));
}

// ---------------------------------------------------------------------------
// Build pair slots: [C,S,S] fp32 -> [S,S] slots of {tex(x), tex(x+1)} fp16.
// Slot x = S-1 zero-pads its second texel (implements zeros padding at x=S).
// ---------------------------------------------------------------------------
__global__ void build_pairs_kernel(const float* __restrict__ src,
                                   unsigned int* __restrict__ dst,
                                   int S) {
    int idx = blockIdx.x * blockDim.x + threadIdx.x;
    int n = S * S;
    if (idx >= n) return;
    int x = idx & (S - 1);           // S is a power of two
    bool has_next = (x + 1 < S);

    float a[NCH], b[NCH];
#pragma unroll
    for (int c = 0; c < NCH; c++) {
        a[c] = src[(size_t)c * n + idx];
        b[c] = has_next ? src[(size_t)c * n + idx + 1] : 0.0f;
    }
    unsigned int r[8];
#pragma unroll
    for (int i = 0; i < 4; i++) {
        __half2 ha = __halves2half2(__float2half_rn(a[2 * i]), __float2half_rn(a[2 * i + 1]));
        __half2 hb = __halves2half2(__float2half_rn(b[2 * i]), __float2half_rn(b[2 * i + 1]));
        r[i]     = *reinterpret_cast<unsigned int*>(&ha);
        r[i + 4] = *reinterpret_cast<unsigned int*>(&hb);
    }
    uint4* d = reinterpret_cast<uint4*>(dst + (size_t)idx * 8);
    d[0] = make_uint4(r[0], r[1], r[2], r[3]);
    d[1] = make_uint4(r[4], r[5], r[6], r[7]);
}

// ---------------------------------------------------------------------------
// One bilinear tap. align_corners=False, grid=uv*2-1  =>  g = uv*S - 0.5.
// Row fetch = ONE aligned LDG.256 from the pair slot at (y, max(x0,0)).
//   x0 >= 0 : slot holds (x0, x1); weights (1-fx, fx); x1==S pad is zero.
//   x0 == -1: slot 0 holds (0, 1) = (x1, .); weights (fx, 0).
// Invalid y rows: registers stay zero (zeros padding).
// ---------------------------------------------------------------------------
template <int S>
__device__ __forceinline__ void sample_pairs(const unsigned int* __restrict__ base,
                                             float u, float v, float2 acc[4]) {
    float gx = u * (float)S - 0.5f;
    float gy = v * (float)S - 0.5f;
    float xf = floorf(gx);
    float yf = floorf(gy);
    int x0 = (int)xf, y0 = (int)yf;
    int y1 = y0 + 1;
    float fx = gx - xf;
    float fy = gy - yf;

    bool lo = (x0 >= 0);
    int  xl = lo ? x0 : 0;
    float wxA = lo ? (1.0f - fx) : fx;
    float wxB = lo ? fx : 0.0f;
    float wy0 = 1.0f - fy;
    float wy1 = fy;

    unsigned int r0[8] = {0, 0, 0, 0, 0, 0, 0, 0};
    unsigned int r1[8] = {0, 0, 0, 0, 0, 0, 0, 0};
    if (y0 >= 0 && y0 < S) ldg256u(base + ((size_t)y0 * S + xl) * 8, r0);
    if (y1 >= 0 && y1 < S) ldg256u(base + ((size_t)y1 * S + xl) * 8, r1);

#pragma unroll
    for (int i = 0; i < 4; i++) {
        float2 A0 = __half22float2(*reinterpret_cast<__half2*>(&r0[i]));
        float2 B0 = __half22float2(*reinterpret_cast<__half2*>(&r0[i + 4]));
        float2 A1 = __half22float2(*reinterpret_cast<__half2*>(&r1[i]));
        float2 B1 = __half22float2(*reinterpret_cast<__half2*>(&r1[i + 4]));
        float tx0 = wxA * A0.x + wxB * B0.x;
        float ty0 = wxA * A0.y + wxB * B0.y;
        float tx1 = wxA * A1.x + wxB * B1.x;
        float ty1 = wxA * A1.y + wxB * B1.y;
        acc[i].x += wy0 * tx0 + wy1 * tx1;
        acc[i].y += wy0 * ty0 + wy1 * ty1;
    }
}

// ---------------------------------------------------------------------------
// Main kernel: 1 thread per pixel, sums 4 mip levels over all 8 channels.
// ---------------------------------------------------------------------------
__global__ void __launch_bounds__(256)
deferred_render_kernel(const float* __restrict__ uv, float* __restrict__ out) {
    int idx = blockIdx.x * blockDim.x + threadIdx.x;
    if (idx >= NPIX) return;

    float u = uv[idx];           // uv_tensor[0,0,:,:]
    float v = uv[NPIX + idx];    // uv_tensor[0,1,:,:]

    float2 acc[4];
#pragma unroll
    for (int i = 0; i < 4; i++) acc[i] = make_float2(0.0f, 0.0f);

    sample_pairs<S0>(g_pairs + POFF0, u, v, acc);
    sample_pairs<S1>(g_pairs + POFF1, u, v, acc);
    sample_pairs<S2>(g_pairs + POFF2, u, v, acc);
    sample_pairs<S3>(g_pairs + POFF3, u, v, acc);

#pragma unroll
    for (int i = 0; i < 4; i++) {
        out[(size_t)(2 * i)     * NPIX + idx] = acc[i].x;
        out[(size_t)(2 * i + 1) * NPIX + idx] = acc[i].y;
    }
}

// ---------------------------------------------------------------------------
// Launch. Inputs per metadata order: uv_tensor, iter_nr, tex0..tex3.
// ---------------------------------------------------------------------------
extern "C" void kernel_launch(void* const* d_in, const int* in_sizes, int n_in,
                              void* d_out, int out_size) {
    const float* uv   = (const float*)d_in[0];
    // d_in[1] = iter_nr (unused)
    const float* tex0 = (const float*)d_in[2];
    const float* tex1 = (const float*)d_in[3];
    const float* tex2 = (const float*)d_in[4];
    const float* tex3 = (const float*)d_in[5];

    unsigned int* scratch;
    cudaGetSymbolAddress((void**)&scratch, g_pairs);

    const int TB = 256;
    build_pairs_kernel<<<(S0 * S0 + TB - 1) / TB, TB>>>(tex0, scratch + POFF0, S0);
    build_pairs_kernel<<<(S1 * S1 + TB - 1) / TB, TB>>>(tex1, scratch + POFF1, S1);
    build_pairs_kernel<<<(S2 * S2 + TB - 1) / TB, TB>>>(tex2, scratch + POFF2, S2);
    build_pairs_kernel<<<(S3 * S3 + TB - 1) / TB, TB>>>(tex3, scratch + POFF3, S3);

    deferred_render_kernel<<<NPIX / TB, TB>>>(uv, (float*)d_out);
}

// round 4
// speedup vs baseline: 2.3848x; 1.0783x over previous
#include <cuda_runtime.h>
#include <cuda_fp16.h>

// Problem constants
#define HH 2048
#define WW 2048
#define NPIX (HH * WW)          // 4,194,304 pixels
#define NCH 8

constexpr int S0 = 1024, S1 = 512, S2 = 256, S3 = 128;
constexpr int N0 = S0 * S0, N1 = S1 * S1, N2 = S2 * S2, N3 = S3 * S3;
// Pair-slot layout: one 32B slot per (y,x) holding fp16 texels (x) and (x+1).
// Slot stride = 8 uints (32B). Offsets in uints:
constexpr size_t POFF0 = 0;
constexpr size_t POFF1 = POFF0 + (size_t)N0 * 8;
constexpr size_t POFF2 = POFF1 + (size_t)N1 * 8;
constexpr size_t POFF3 = POFF2 + (size_t)N2 * 8;
constexpr size_t PAIR_ELEMS = POFF3 + (size_t)N3 * 8;   // 44.56 MB

__device__ __align__(128) unsigned int g_pairs[PAIR_ELEMS];

// ---------------------------------------------------------------------------
// 256-bit load (sm_100+), 32B-aligned: one instruction, one 32B sector.
// ---------------------------------------------------------------------------
__device__ __forceinline__ void ldg256u(const unsigned int* __restrict__ p,
                                        unsigned int r[8]) {
    asm volatile("ld.global.nc.v8.b32 {%0,%1,%2,%3,%4,%5,%6,%7}, [%8];"
                 : "=r"(r[0]), "=r"(r[1]), "=r"(r[2]), "=r"(r[3]),
                   "=r"(r[4]), "=r"(r[5]), "=r"(r[6]), "=r"(r[7])
                 : "l"(p));
}

// ---------------------------------------------------------------------------
// Pair-slot builder for one texel index of one level.
// ---------------------------------------------------------------------------
__device__ __forceinline__ void build_one(const float* __restrict__ src,
                                          unsigned int* __restrict__ dst,
                                          int S, int idx) {
    int n = S * S;
    int x = idx & (S - 1);           // S is a power of two
    bool has_next = (x + 1 < S);

    float a[NCH], b[NCH];
#pragma unroll
    for (int c = 0; c < NCH; c++) {
        a[c] = src[(size_t)c * n + idx];
        b[c] = has_next ? src[(size_t)c * n + idx + 1] : 0.0f;
    }
    unsigned int r[8];
#pragma unroll
    for (int i = 0; i < 4; i++) {
        __half2 ha = __halves2half2(__float2half_rn(a[2 * i]), __float2half_rn(a[2 * i + 1]));
        __half2 hb = __halves2half2(__float2half_rn(b[2 * i]), __float2half_rn(b[2 * i + 1]));
        r[i]     = *reinterpret_cast<unsigned int*>(&ha);
        r[i + 4] = *reinterpret_cast<unsigned int*>(&hb);
    }
    uint4* d = reinterpret_cast<uint4*>(dst + (size_t)idx * 8);
    d[0] = make_uint4(r[0], r[1], r[2], r[3]);
    d[1] = make_uint4(r[4], r[5], r[6], r[7]);
}

// Single fused prepass over all four levels.
__global__ void __launch_bounds__(256)
build_all_kernel(const float* __restrict__ t0, const float* __restrict__ t1,
                 const float* __restrict__ t2, const float* __restrict__ t3,
                 unsigned int* __restrict__ dst) {
    int idx = blockIdx.x * blockDim.x + threadIdx.x;
    if (idx < N0)                 { build_one(t0, dst + POFF0, S0, idx); return; }
    idx -= N0;
    if (idx < N1)                 { build_one(t1, dst + POFF1, S1, idx); return; }
    idx -= N1;
    if (idx < N2)                 { build_one(t2, dst + POFF2, S2, idx); return; }
    idx -= N2;
    if (idx < N3)                 { build_one(t3, dst + POFF3, S3, idx); }
}

// ---------------------------------------------------------------------------
// Coord/weight computation for one level. align_corners=False, grid=uv*2-1
// => g = uv*S - 0.5.  Addresses are clamped to valid slots; zeros padding is
// realized purely through zeroed weights, so loads are UNCONDITIONAL.
//   x0 >= 0 : slot (y, x0) holds (x0, x0+1); weights (1-fx, fx). x0+1==S pad=0.
//   x0 == -1: slot (y, 0) holds (0, 1); weights (fx, 0).
//   y row out of range: weight 0 (address clamped into range).
// ---------------------------------------------------------------------------
template <int S>
__device__ __forceinline__ void coords(float u, float v,
                                       size_t& o0, size_t& o1,
                                       float& wxA, float& wxB,
                                       float& wy0, float& wy1) {
    float gx = u * (float)S - 0.5f;
    float gy = v * (float)S - 0.5f;
    float xf = floorf(gx);
    float yf = floorf(gy);
    int x0 = (int)xf, y0 = (int)yf;
    int y1 = y0 + 1;
    float fx = gx - xf;
    float fy = gy - yf;

    bool lo = (x0 >= 0);
    int  xl = lo ? x0 : 0;
    wxA = lo ? (1.0f - fx) : fx;
    wxB = lo ? fx : 0.0f;

    bool v0 = (y0 >= 0) & (y0 < S);
    bool v1 = (y1 >= 0) & (y1 < S);
    wy0 = v0 ? (1.0f - fy) : 0.0f;
    wy1 = v1 ? fy : 0.0f;
    int yc0 = v0 ? y0 : 0;
    int yc1 = v1 ? y1 : (S - 1);

    o0 = ((size_t)yc0 * S + xl) * 8;
    o1 = ((size_t)yc1 * S + xl) * 8;
}

// Accumulate one level's contribution from its two row registers.
__device__ __forceinline__ void accum_level(const unsigned int r0[8],
                                            const unsigned int r1[8],
                                            float wxA, float wxB,
                                            float wy0, float wy1,
                                            float2 acc[4]) {
#pragma unroll
    for (int i = 0; i < 4; i++) {
        float2 A0 = __half22float2(*reinterpret_cast<const __half2*>(&r0[i]));
        float2 B0 = __half22float2(*reinterpret_cast<const __half2*>(&r0[i + 4]));
        float2 A1 = __half22float2(*reinterpret_cast<const __half2*>(&r1[i]));
        float2 B1 = __half22float2(*reinterpret_cast<const __half2*>(&r1[i + 4]));
        float tx0 = wxA * A0.x + wxB * B0.x;
        float ty0 = wxA * A0.y + wxB * B0.y;
        float tx1 = wxA * A1.x + wxB * B1.x;
        float ty1 = wxA * A1.y + wxB * B1.y;
        acc[i].x += wy0 * tx0 + wy1 * tx1;
        acc[i].y += wy0 * ty0 + wy1 * ty1;
    }
}

// ---------------------------------------------------------------------------
// Main kernel: 1 thread per pixel. All coords first, then ALL 8 LDG.256
// back-to-back (max per-thread MLP), then math.
// ---------------------------------------------------------------------------
__global__ void __launch_bounds__(128)
deferred_render_kernel(const float* __restrict__ uv, float* __restrict__ out) {
    int idx = blockIdx.x * blockDim.x + threadIdx.x;

    float u = uv[idx];           // uv_tensor[0,0,:,:]
    float v = uv[NPIX + idx];    // uv_tensor[0,1,:,:]

    size_t o[8];
    float wxA[4], wxB[4], wy0[4], wy1[4];
    coords<S0>(u, v, o[0], o[1], wxA[0], wxB[0], wy0[0], wy1[0]);
    coords<S1>(u, v, o[2], o[3], wxA[1], wxB[1], wy0[1], wy1[1]);
    coords<S2>(u, v, o[4], o[5], wxA[2], wxB[2], wy0[2], wy1[2]);
    coords<S3>(u, v, o[6], o[7], wxA[3], wxB[3], wy0[3], wy1[3]);

    unsigned int r[8][8];
    ldg256u(g_pairs + POFF0 + o[0], r[0]);
    ldg256u(g_pairs + POFF0 + o[1], r[1]);
    ldg256u(g_pairs + POFF1 + o[2], r[2]);
    ldg256u(g_pairs + POFF1 + o[3], r[3]);
    ldg256u(g_pairs + POFF2 + o[4], r[4]);
    ldg256u(g_pairs + POFF2 + o[5], r[5]);
    ldg256u(g_pairs + POFF3 + o[6], r[6]);
    ldg256u(g_pairs + POFF3 + o[7], r[7]);

    float2 acc[4];
#pragma unroll
    for (int i = 0; i < 4; i++) acc[i] = make_float2(0.0f, 0.0f);

    accum_level(r[0], r[1], wxA[0], wxB[0], wy0[0], wy1[0], acc);
    accum_level(r[2], r[3], wxA[1], wxB[1], wy0[1], wy1[1], acc);
    accum_level(r[4], r[5], wxA[2], wxB[2], wy0[2], wy1[2], acc);
    accum_level(r[6], r[7], wxA[3], wxB[3], wy0[3], wy1[3], acc);

#pragma unroll
    for (int i = 0; i < 4; i++) {
        out[(size_t)(2 * i)     * NPIX + idx] = acc[i].x;
        out[(size_t)(2 * i + 1) * NPIX + idx] = acc[i].y;
    }
}

// ---------------------------------------------------------------------------
// Launch. Inputs per metadata order: uv_tensor, iter_nr, tex0..tex3.
// ---------------------------------------------------------------------------
extern "C" void kernel_launch(void* const* d_in, const int* in_sizes, int n_in,
                              void* d_out, int out_size) {
    const float* uv   = (const float*)d_in[0];
    // d_in[1] = iter_nr (unused)
    const float* tex0 = (const float*)d_in[2];
    const float* tex1 = (const float*)d_in[3];
    const float* tex2 = (const float*)d_in[4];
    const float* tex3 = (const float*)d_in[5];

    unsigned int* scratch;
    cudaGetSymbolAddress((void**)&scratch, g_pairs);

    const int TOTAL = N0 + N1 + N2 + N3;
    build_all_kernel<<<(TOTAL + 255) / 256, 256>>>(tex0, tex1, tex2, tex3, scratch);

    deferred_render_kernel<<<NPIX / 128, 128>>>(uv, (float*)d_out);
}

// round 5
// speedup vs baseline: 2.4402x; 1.0233x over previous
#include <cuda_runtime.h>
#include <cuda_fp16.h>

// Problem constants
#define HH 2048
#define WW 2048
#define NPIX (HH * WW)          // 4,194,304 pixels
#define NCH 8

constexpr int S0 = 1024, S1 = 512, S2 = 256, S3 = 128;
constexpr int N0 = S0 * S0, N1 = S1 * S1, N2 = S2 * S2, N3 = S3 * S3;
// Pair-slot layout: one 32B slot per (y,x) holding fp16 texels (x) and (x+1).
// Slot stride = 8 uints (32B). Offsets in uints:
constexpr unsigned POFF0 = 0;
constexpr unsigned POFF1 = POFF0 + (unsigned)N0 * 8;
constexpr unsigned POFF2 = POFF1 + (unsigned)N1 * 8;
constexpr unsigned POFF3 = POFF2 + (unsigned)N2 * 8;
constexpr size_t PAIR_ELEMS = (size_t)POFF3 + (size_t)N3 * 8;   // 44.56 MB

__device__ __align__(128) unsigned int g_pairs[PAIR_ELEMS];

// ---------------------------------------------------------------------------
// 256-bit load (sm_100+), 32B-aligned: one instruction, one 32B sector.
// ---------------------------------------------------------------------------
__device__ __forceinline__ void ldg256u(const unsigned int* __restrict__ p,
                                        unsigned int r[8]) {
    asm volatile("ld.global.nc.v8.b32 {%0,%1,%2,%3,%4,%5,%6,%7}, [%8];"
                 : "=r"(r[0]), "=r"(r[1]), "=r"(r[2]), "=r"(r[3]),
                   "=r"(r[4]), "=r"(r[5]), "=r"(r[6]), "=r"(r[7])
                 : "l"(p));
}

// ---------------------------------------------------------------------------
// Pair-slot builder for one texel index of one level.
// ---------------------------------------------------------------------------
__device__ __forceinline__ void build_one(const float* __restrict__ src,
                                          unsigned int* __restrict__ dst,
                                          int S, int idx) {
    int n = S * S;
    int x = idx & (S - 1);           // S is a power of two
    bool has_next = (x + 1 < S);

    float a[NCH], b[NCH];
#pragma unroll
    for (int c = 0; c < NCH; c++) {
        a[c] = src[(size_t)c * n + idx];
        b[c] = has_next ? src[(size_t)c * n + idx + 1] : 0.0f;
    }
    unsigned int r[8];
#pragma unroll
    for (int i = 0; i < 4; i++) {
        __half2 ha = __halves2half2(__float2half_rn(a[2 * i]), __float2half_rn(a[2 * i + 1]));
        __half2 hb = __halves2half2(__float2half_rn(b[2 * i]), __float2half_rn(b[2 * i + 1]));
        r[i]     = *reinterpret_cast<unsigned int*>(&ha);
        r[i + 4] = *reinterpret_cast<unsigned int*>(&hb);
    }
    uint4* d = reinterpret_cast<uint4*>(dst + (size_t)idx * 8);
    d[0] = make_uint4(r[0], r[1], r[2], r[3]);
    d[1] = make_uint4(r[4], r[5], r[6], r[7]);
}

// Single fused prepass over all four levels.
__global__ void __launch_bounds__(256)
build_all_kernel(const float* __restrict__ t0, const float* __restrict__ t1,
                 const float* __restrict__ t2, const float* __restrict__ t3,
                 unsigned int* __restrict__ dst) {
    int idx = blockIdx.x * blockDim.x + threadIdx.x;
    if (idx < N0)                 { build_one(t0, dst + POFF0, S0, idx); return; }
    idx -= N0;
    if (idx < N1)                 { build_one(t1, dst + POFF1, S1, idx); return; }
    idx -= N1;
    if (idx < N2)                 { build_one(t2, dst + POFF2, S2, idx); return; }
    idx -= N2;
    if (idx < N3)                 { build_one(t3, dst + POFF3, S3, idx); }
}

// ---------------------------------------------------------------------------
// Coord/weight computation for one level. align_corners=False, grid=uv*2-1
// => g = uv*S - 0.5.  Addresses are clamped to valid slots; zeros padding is
// realized purely through zeroed weights, so loads are UNCONDITIONAL.
// 32-bit offsets (max 8.4M uints < 2^31) to cut index register pressure.
// ---------------------------------------------------------------------------
template <int S>
__device__ __forceinline__ void coords(float u, float v,
                                       unsigned& o0, unsigned& o1,
                                       float& wxA, float& wxB,
                                       float& wy0, float& wy1) {
    float gx = u * (float)S - 0.5f;
    float gy = v * (float)S - 0.5f;
    float xf = floorf(gx);
    float yf = floorf(gy);
    int x0 = (int)xf, y0 = (int)yf;
    int y1 = y0 + 1;
    float fx = gx - xf;
    float fy = gy - yf;

    bool lo = (x0 >= 0);
    int  xl = lo ? x0 : 0;
    wxA = lo ? (1.0f - fx) : fx;
    wxB = lo ? fx : 0.0f;

    bool v0 = (y0 >= 0) & (y0 < S);
    bool v1 = (y1 >= 0) & (y1 < S);
    wy0 = v0 ? (1.0f - fy) : 0.0f;
    wy1 = v1 ? fy : 0.0f;
    int yc0 = v0 ? y0 : 0;
    int yc1 = v1 ? y1 : (S - 1);

    o0 = ((unsigned)(yc0 * S + xl)) * 8u;
    o1 = ((unsigned)(yc1 * S + xl)) * 8u;
}

// Accumulate one level's contribution from its two row registers.
__device__ __forceinline__ void accum_level(const unsigned int r0[8],
                                            const unsigned int r1[8],
                                            float wxA, float wxB,
                                            float wy0, float wy1,
                                            float2 acc[4]) {
#pragma unroll
    for (int i = 0; i < 4; i++) {
        float2 A0 = __half22float2(*reinterpret_cast<const __half2*>(&r0[i]));
        float2 B0 = __half22float2(*reinterpret_cast<const __half2*>(&r0[i + 4]));
        float2 A1 = __half22float2(*reinterpret_cast<const __half2*>(&r1[i]));
        float2 B1 = __half22float2(*reinterpret_cast<const __half2*>(&r1[i + 4]));
        float tx0 = wxA * A0.x + wxB * B0.x;
        float ty0 = wxA * A0.y + wxB * B0.y;
        float tx1 = wxA * A1.x + wxB * B1.x;
        float ty1 = wxA * A1.y + wxB * B1.y;
        acc[i].x += wy0 * tx0 + wy1 * tx1;
        acc[i].y += wy0 * ty0 + wy1 * ty1;
    }
}

// Process two levels: coords, 4 batched loads, accumulate.
template <int SA, int SB>
__device__ __forceinline__ void do_two_levels(unsigned pbaseA, unsigned pbaseB,
                                              float u, float v, float2 acc[4]) {
    unsigned oA0, oA1, oB0, oB1;
    float axA, axB, ay0, ay1;
    float bxA, bxB, by0, by1;
    coords<SA>(u, v, oA0, oA1, axA, axB, ay0, ay1);
    coords<SB>(u, v, oB0, oB1, bxA, bxB, by0, by1);

    unsigned int r0[8], r1[8], r2[8], r3[8];
    ldg256u(g_pairs + pbaseA + oA0, r0);
    ldg256u(g_pairs + pbaseA + oA1, r1);
    ldg256u(g_pairs + pbaseB + oB0, r2);
    ldg256u(g_pairs + pbaseB + oB1, r3);

    accum_level(r0, r1, axA, axB, ay0, ay1, acc);
    accum_level(r2, r3, bxA, bxB, by0, by1, acc);
}

// ---------------------------------------------------------------------------
// Main kernel: 1 thread per pixel, levels processed in two halves to keep
// register pressure <= 42 (12 CTAs/SM => 75% occupancy).
// ---------------------------------------------------------------------------
__global__ void __launch_bounds__(128, 12)
deferred_render_kernel(const float* __restrict__ uv, float* __restrict__ out) {
    int idx = blockIdx.x * blockDim.x + threadIdx.x;

    float u = __ldcs(uv + idx);          // streaming: don't pollute L2
    float v = __ldcs(uv + NPIX + idx);

    float2 acc[4];
#pragma unroll
    for (int i = 0; i < 4; i++) acc[i] = make_float2(0.0f, 0.0f);

    do_two_levels<S0, S1>(POFF0, POFF1, u, v, acc);
    do_two_levels<S2, S3>(POFF2, POFF3, u, v, acc);

#pragma unroll
    for (int i = 0; i < 4; i++) {
        __stcs(out + (size_t)(2 * i)     * NPIX + idx, acc[i].x);
        __stcs(out + (size_t)(2 * i + 1) * NPIX + idx, acc[i].y);
    }
}

// ---------------------------------------------------------------------------
// Launch. Inputs per metadata order: uv_tensor, iter_nr, tex0..tex3.
// ---------------------------------------------------------------------------
extern "C" void kernel_launch(void* const* d_in, const int* in_sizes, int n_in,
                              void* d_out, int out_size) {
    const float* uv   = (const float*)d_in[0];
    // d_in[1] = iter_nr (unused)
    const float* tex0 = (const float*)d_in[2];
    const float* tex1 = (const float*)d_in[3];
    const float* tex2 = (const float*)d_in[4];
    const float* tex3 = (const float*)d_in[5];

    unsigned int* scratch;
    cudaGetSymbolAddress((void**)&scratch, g_pairs);

    const int TOTAL = N0 + N1 + N2 + N3;
    build_all_kernel<<<(TOTAL + 255) / 256, 256>>>(tex0, tex1, tex2, tex3, scratch);

    deferred_render_kernel<<<NPIX / 128, 128>>>(uv, (float*)d_out);
}